// round 1
// baseline (speedup 1.0000x reference)
#include <cuda_runtime.h>
#include <cuda_fp16.h>

// Fan-beam CT forward projector.
// image [8,512,512] f32, views [360] f32 -> out [8,360,768] f32.
//
// Strategy:
//   Kernel 1: repack image into zero-padded, batch-interleaved fp16:
//             g_packed[py][px] = 8 halves (one per batch) = one uint4 (16B).
//             2-pixel zero border makes all boundary gathers implicit zeros.
//   Kernel 2: thread = (view, detector). Clip ray against image square,
//             march only in-support samples. Per sample: 4x LDG.128 fetches
//             all 8 batches of all 4 bilinear corners; fp32 accumulate.

namespace {
constexpr int IMG    = 512;
constexpr int PAD    = 2;
constexpr int PADN   = IMG + 2 * PAD;   // 516
constexpr int NB     = 8;
constexpr int NDET   = 768;
constexpr int NVIEWS = 360;
constexpr int NSAMP  = 768;

constexpr double PIX_D = 0.7433;
constexpr double DET_D = 1.2858;
constexpr double ISO_D = 595.0;
constexpr double SDD_D = 595.0 + 490.6;
constexpr double FOV_D = IMG * PIX_D * 0.70710678;
constexpr double T0_D  = ISO_D - FOV_D;
constexpr double DT_D  = 2.0 * FOV_D / NSAMP;

constexpr float DGAMMA  = (float)(DET_D / SDD_D);
constexpr float T0F     = (float)T0_D;
constexpr float DTF     = (float)DT_D;
constexpr float INV_PIX = (float)(1.0 / PIX_D);
constexpr float PI_F    = 3.14159265358979323846f;
}

// 516*516 pixel-groups, 16 bytes each (8 batches x fp16) = 4.26 MB scratch.
__device__ uint4 g_packed[PADN * PADN];

__global__ void repack_kernel(const float* __restrict__ img) {
    int idx = blockIdx.x * blockDim.x + threadIdx.x;
    if (idx >= PADN * PADN) return;
    int py = idx / PADN;
    int px = idx - py * PADN;
    int y = py - PAD;
    int x = px - PAD;
    uint4 u = make_uint4(0u, 0u, 0u, 0u);
    if ((unsigned)y < (unsigned)IMG && (unsigned)x < (unsigned)IMG) {
        int base = y * IMG + x;
        const int BS = IMG * IMG;
        __half2 h0 = __floats2half2_rn(img[base + 0 * BS], img[base + 1 * BS]);
        __half2 h1 = __floats2half2_rn(img[base + 2 * BS], img[base + 3 * BS]);
        __half2 h2 = __floats2half2_rn(img[base + 4 * BS], img[base + 5 * BS]);
        __half2 h3 = __floats2half2_rn(img[base + 6 * BS], img[base + 7 * BS]);
        u.x = *reinterpret_cast<unsigned*>(&h0);
        u.y = *reinterpret_cast<unsigned*>(&h1);
        u.z = *reinterpret_cast<unsigned*>(&h2);
        u.w = *reinterpret_cast<unsigned*>(&h3);
    }
    g_packed[idx] = u;
}

__device__ __forceinline__ void acc8(uint4 r, float w, float acc[NB]) {
    __half2 h0 = *reinterpret_cast<__half2*>(&r.x);
    __half2 h1 = *reinterpret_cast<__half2*>(&r.y);
    __half2 h2 = *reinterpret_cast<__half2*>(&r.z);
    __half2 h3 = *reinterpret_cast<__half2*>(&r.w);
    float2 f0 = __half22float2(h0);
    float2 f1 = __half22float2(h1);
    float2 f2 = __half22float2(h2);
    float2 f3 = __half22float2(h3);
    acc[0] = fmaf(f0.x, w, acc[0]);
    acc[1] = fmaf(f0.y, w, acc[1]);
    acc[2] = fmaf(f1.x, w, acc[2]);
    acc[3] = fmaf(f1.y, w, acc[3]);
    acc[4] = fmaf(f2.x, w, acc[4]);
    acc[5] = fmaf(f2.y, w, acc[5]);
    acc[6] = fmaf(f3.x, w, acc[6]);
    acc[7] = fmaf(f3.y, w, acc[7]);
}

__global__ __launch_bounds__(128) void proj_kernel(const float* __restrict__ views,
                                                   float* __restrict__ out) {
    const int d = blockIdx.x * 128 + threadIdx.x;  // detector
    const int v = blockIdx.y;                      // view

    const float beta  = __ldg(&views[v]);
    const float gamma = ((float)d - (float)(NDET - 1) * 0.5f) * DGAMMA;

    float sb, cb;
    sincosf(beta, &sb, &cb);
    const float sx = (float)ISO_D * cb;
    const float sy = (float)ISO_D * sb;

    float diry, dirx;
    sincosf(beta + PI_F + gamma, &diry, &dirx);

    // Pixel-space ray: fx(i) = ax + bx*i (i = sample index)
    const float tstart = T0F + 0.5f * DTF;
    const float bx = dirx * DTF * INV_PIX;
    const float by = diry * DTF * INV_PIX;
    const float ax = (sx + dirx * tstart) * INV_PIX + (float)(IMG - 1) * 0.5f;
    const float ay = (sy + diry * tstart) * INV_PIX + (float)(IMG - 1) * 0.5f;

    // Clip sample range to the support box fx,fy in [-1.5, 512.5]
    float flo = 0.0f, fhi = (float)(NSAMP - 1);
    const float LOB = -1.5f, HIB = (float)IMG + 0.5f;
    if (fabsf(bx) > 1e-7f) {
        float r  = 1.0f / bx;
        float t1 = (LOB - ax) * r;
        float t2 = (HIB - ax) * r;
        flo = fmaxf(flo, fminf(t1, t2));
        fhi = fminf(fhi, fmaxf(t1, t2));
    } else if (ax < LOB || ax > HIB) {
        fhi = -1.0f;
    }
    if (fabsf(by) > 1e-7f) {
        float r  = 1.0f / by;
        float t1 = (LOB - ay) * r;
        float t2 = (HIB - ay) * r;
        flo = fmaxf(flo, fminf(t1, t2));
        fhi = fminf(fhi, fmaxf(t1, t2));
    } else if (ay < LOB || ay > HIB) {
        fhi = -1.0f;
    }
    int i0 = max(0, (int)ceilf(flo) - 1);
    int i1 = min(NSAMP, (int)floorf(fhi) + 2);

    float acc[NB];
#pragma unroll
    for (int b = 0; b < NB; b++) acc[b] = 0.0f;

    const uint4* __restrict__ pk = g_packed;

    for (int i = i0; i < i1; ++i) {
        float fi = (float)i;
        float fx = fmaf(fi, bx, ax);
        float fy = fmaf(fi, by, ay);
        float x0f = floorf(fx);
        float y0f = floorf(fy);
        float wx = fx - x0f;
        float wy = fy - y0f;
        int x0 = (int)x0f;
        int y0 = (int)y0f;
        // Clamp into the zero-padded frame: any OOB footprint reads zeros.
        x0 = min(max(x0, -PAD), IMG);
        y0 = min(max(y0, -PAD), IMG);

        const uint4* p = pk + (y0 + PAD) * PADN + (x0 + PAD);
        uint4 r00 = __ldg(p);
        uint4 r01 = __ldg(p + 1);
        uint4 r10 = __ldg(p + PADN);
        uint4 r11 = __ldg(p + PADN + 1);

        float wx1 = 1.0f - wx;
        float wy1 = 1.0f - wy;
        float w00 = wx1 * wy1;
        float w01 = wx * wy1;
        float w10 = wx1 * wy;
        float w11 = wx * wy;

        acc8(r00, w00, acc);
        acc8(r01, w01, acc);
        acc8(r10, w10, acc);
        acc8(r11, w11, acc);
    }

    // out[b][v][d]
#pragma unroll
    for (int b = 0; b < NB; b++) {
        out[(b * NVIEWS + v) * NDET + d] = acc[b] * DTF;
    }
}

extern "C" void kernel_launch(void* const* d_in, const int* in_sizes, int n_in,
                              void* d_out, int out_size) {
    const float* image = (const float*)d_in[0];
    const float* views = (const float*)d_in[1];
    float* out = (float*)d_out;

    repack_kernel<<<(PADN * PADN + 255) / 256, 256>>>(image);
    proj_kernel<<<dim3(NDET / 128, NVIEWS), 128>>>(views, out);
}

// round 2
// speedup vs baseline: 1.0763x; 1.0763x over previous
#include <cuda_runtime.h>
#include <cuda_fp16.h>

// Fan-beam CT forward projector.
// image [8,512,512] f32, views [360] f32 -> out [8,360,768] f32.
//
// R2: dual-layout packed image (row-major + transposed). Each warp samples the
// layout whose contiguous axis matches its perpendicular (lane-spread)
// direction, minimizing L1 wavefront replays. Sample loop unrolled x2 with
// grouped loads for MLP=8.

namespace {
constexpr int IMG    = 512;
constexpr int PAD    = 2;
constexpr int PADN   = IMG + 2 * PAD;   // 516
constexpr int NB     = 8;
constexpr int NDET   = 768;
constexpr int NVIEWS = 360;
constexpr int NSAMP  = 768;

constexpr double PIX_D = 0.7433;
constexpr double DET_D = 1.2858;
constexpr double ISO_D = 595.0;
constexpr double SDD_D = 595.0 + 490.6;
constexpr double FOV_D = IMG * PIX_D * 0.70710678;
constexpr double T0_D  = ISO_D - FOV_D;
constexpr double DT_D  = 2.0 * FOV_D / NSAMP;

constexpr float DGAMMA  = (float)(DET_D / SDD_D);
constexpr float T0F     = (float)T0_D;
constexpr float DTF     = (float)DT_D;
constexpr float INV_PIX = (float)(1.0 / PIX_D);
constexpr float PI_F    = 3.14159265358979323846f;
}

// 516*516 pixel-groups, 16 bytes each (8 batches x fp16) = 4.26 MB per copy.
__device__ uint4 g_packed[PADN * PADN];   // [y][x]
__device__ uint4 g_packedT[PADN * PADN];  // [x][y]

__global__ void repack_kernel(const float* __restrict__ img) {
    int idx = blockIdx.x * blockDim.x + threadIdx.x;
    if (idx >= PADN * PADN) return;
    int py = idx / PADN;
    int px = idx - py * PADN;
    int y = py - PAD;
    int x = px - PAD;
    uint4 u = make_uint4(0u, 0u, 0u, 0u);
    if ((unsigned)y < (unsigned)IMG && (unsigned)x < (unsigned)IMG) {
        int base = y * IMG + x;
        const int BS = IMG * IMG;
        __half2 h0 = __floats2half2_rn(img[base + 0 * BS], img[base + 1 * BS]);
        __half2 h1 = __floats2half2_rn(img[base + 2 * BS], img[base + 3 * BS]);
        __half2 h2 = __floats2half2_rn(img[base + 4 * BS], img[base + 5 * BS]);
        __half2 h3 = __floats2half2_rn(img[base + 6 * BS], img[base + 7 * BS]);
        u.x = *reinterpret_cast<unsigned*>(&h0);
        u.y = *reinterpret_cast<unsigned*>(&h1);
        u.z = *reinterpret_cast<unsigned*>(&h2);
        u.w = *reinterpret_cast<unsigned*>(&h3);
    }
    g_packed[py * PADN + px] = u;
    g_packedT[px * PADN + py] = u;
}

__device__ __forceinline__ void acc8(uint4 r, float w, float acc[NB]) {
    __half2 h0 = *reinterpret_cast<__half2*>(&r.x);
    __half2 h1 = *reinterpret_cast<__half2*>(&r.y);
    __half2 h2 = *reinterpret_cast<__half2*>(&r.z);
    __half2 h3 = *reinterpret_cast<__half2*>(&r.w);
    float2 f0 = __half22float2(h0);
    float2 f1 = __half22float2(h1);
    float2 f2 = __half22float2(h2);
    float2 f3 = __half22float2(h3);
    acc[0] = fmaf(f0.x, w, acc[0]);
    acc[1] = fmaf(f0.y, w, acc[1]);
    acc[2] = fmaf(f1.x, w, acc[2]);
    acc[3] = fmaf(f1.y, w, acc[3]);
    acc[4] = fmaf(f2.x, w, acc[4]);
    acc[5] = fmaf(f2.y, w, acc[5]);
    acc[6] = fmaf(f3.x, w, acc[6]);
    acc[7] = fmaf(f3.y, w, acc[7]);
}

// One bilinear sample: compute address + 4 corner loads, deferred accumulate.
struct Sample {
    uint4 r00, r01, r10, r11;
    float w00, w01, w10, w11;
};

__device__ __forceinline__ void sample_load(const uint4* __restrict__ pk,
                                            float fu, float fv, Sample& s) {
    // fu = slow axis coordinate, fv = fast (contiguous) axis coordinate
    float u0f = floorf(fu);
    float v0f = floorf(fv);
    float wu = fu - u0f;
    float wv = fv - v0f;
    int u0 = (int)u0f;
    int v0 = (int)v0f;
    u0 = min(max(u0, -PAD), IMG);
    v0 = min(max(v0, -PAD), IMG);
    const uint4* p = pk + (u0 + PAD) * PADN + (v0 + PAD);
    s.r00 = __ldg(p);
    s.r01 = __ldg(p + 1);
    s.r10 = __ldg(p + PADN);
    s.r11 = __ldg(p + PADN + 1);
    float wu1 = 1.0f - wu;
    float wv1 = 1.0f - wv;
    s.w00 = wu1 * wv1;  // (u0, v0)
    s.w01 = wu1 * wv;   // (u0, v0+1)
    s.w10 = wu * wv1;   // (u0+1, v0)
    s.w11 = wu * wv;
}

__device__ __forceinline__ void sample_acc(const Sample& s, float acc[NB]) {
    acc8(s.r00, s.w00, acc);
    acc8(s.r01, s.w01, acc);
    acc8(s.r10, s.w10, acc);
    acc8(s.r11, s.w11, acc);
}

__global__ __launch_bounds__(128) void proj_kernel(const float* __restrict__ views,
                                                   float* __restrict__ out) {
    const int d = blockIdx.x * 128 + threadIdx.x;  // detector
    const int v = blockIdx.y;                      // view

    const float beta  = __ldg(&views[v]);
    const float gamma = ((float)d - (float)(NDET - 1) * 0.5f) * DGAMMA;

    float sb, cb;
    sincosf(beta, &sb, &cb);
    const float sx = (float)ISO_D * cb;
    const float sy = (float)ISO_D * sb;

    float diry, dirx;
    sincosf(beta + PI_F + gamma, &diry, &dirx);

    // Pixel-space ray: fx(i) = ax + bx*i (i = sample index)
    const float tstart = T0F + 0.5f * DTF;
    float bx = dirx * DTF * INV_PIX;
    float by = diry * DTF * INV_PIX;
    float ax = (sx + dirx * tstart) * INV_PIX + (float)(IMG - 1) * 0.5f;
    float ay = (sy + diry * tstart) * INV_PIX + (float)(IMG - 1) * 0.5f;

    // Clip sample range to the support box fx,fy in [-1.5, 512.5]
    float flo = 0.0f, fhi = (float)(NSAMP - 1);
    const float LOB = -1.5f, HIB = (float)IMG + 0.5f;
    if (fabsf(bx) > 1e-7f) {
        float r  = 1.0f / bx;
        float t1 = (LOB - ax) * r;
        float t2 = (HIB - ax) * r;
        flo = fmaxf(flo, fminf(t1, t2));
        fhi = fminf(fhi, fmaxf(t1, t2));
    } else if (ax < LOB || ax > HIB) {
        fhi = -1.0f;
    }
    if (fabsf(by) > 1e-7f) {
        float r  = 1.0f / by;
        float t1 = (LOB - ay) * r;
        float t2 = (HIB - ay) * r;
        flo = fmaxf(flo, fminf(t1, t2));
        fhi = fminf(fhi, fmaxf(t1, t2));
    } else if (ay < LOB || ay > HIB) {
        fhi = -1.0f;
    }
    int i0 = max(0, (int)ceilf(flo) - 1);
    int i1 = min(NSAMP, (int)floorf(fhi) + 2);

    // Layout choice: lanes (adjacent detectors) spread perpendicular to the
    // ray. If the ray runs mostly along x, lanes spread along y -> use the
    // transposed layout so the spread is along the contiguous axis.
    // Warp-uniform decision (lane 0's ray).
    bool wantT = fabsf(bx) >= fabsf(by);
    wantT = __shfl_sync(0xffffffffu, (int)wantT, 0) != 0;

    const uint4* __restrict__ pk;
    float au, bu, av, bv;  // u = slow axis, v = fast axis of chosen layout
    if (wantT) {
        pk = g_packedT;     // [x][y]: slow = x, fast = y
        au = ax; bu = bx;
        av = ay; bv = by;
    } else {
        pk = g_packed;      // [y][x]: slow = y, fast = x
        au = ay; bu = by;
        av = ax; bv = bx;
    }

    float acc[NB];
#pragma unroll
    for (int b = 0; b < NB; b++) acc[b] = 0.0f;

    int i = i0;
    for (; i + 2 <= i1; i += 2) {
        float f0 = (float)i;
        float f1 = (float)(i + 1);
        Sample s0, s1;
        sample_load(pk, fmaf(f0, bu, au), fmaf(f0, bv, av), s0);
        sample_load(pk, fmaf(f1, bu, au), fmaf(f1, bv, av), s1);
        sample_acc(s0, acc);
        sample_acc(s1, acc);
    }
    if (i < i1) {
        float f0 = (float)i;
        Sample s0;
        sample_load(pk, fmaf(f0, bu, au), fmaf(f0, bv, av), s0);
        sample_acc(s0, acc);
    }

    // out[b][v][d]
#pragma unroll
    for (int b = 0; b < NB; b++) {
        out[(b * NVIEWS + v) * NDET + d] = acc[b] * DTF;
    }
}

extern "C" void kernel_launch(void* const* d_in, const int* in_sizes, int n_in,
                              void* d_out, int out_size) {
    const float* image = (const float*)d_in[0];
    const float* views = (const float*)d_in[1];
    float* out = (float*)d_out;

    repack_kernel<<<(PADN * PADN + 255) / 256, 256>>>(image);
    proj_kernel<<<dim3(NDET / 128, NVIEWS), 128>>>(views, out);
}

// round 3
// speedup vs baseline: 1.2917x; 1.2002x over previous
#include <cuda_runtime.h>
#include <cuda_fp16.h>

// Fan-beam CT forward projector.
// image [8,512,512] f32, views [360] f32 -> out [8,360,768] f32.
//
// R3: warp = 8 detectors x 4 sample-phases -> compact ~7x4 px warp footprint
// (vs 28x1 px line) to cut L1 wavefront replays on diagonal views.
// Dual-layout (row-major + transposed) packed fp16 image retained for
// axis-aligned views. shfl_xor reduction merges the 4 sample-phase partials.

namespace {
constexpr int IMG    = 512;
constexpr int PAD    = 2;
constexpr int PADN   = IMG + 2 * PAD;   // 516
constexpr int NB     = 8;
constexpr int NDET   = 768;
constexpr int NVIEWS = 360;
constexpr int NSAMP  = 768;

constexpr double PIX_D = 0.7433;
constexpr double DET_D = 1.2858;
constexpr double ISO_D = 595.0;
constexpr double SDD_D = 595.0 + 490.6;
constexpr double FOV_D = IMG * PIX_D * 0.70710678;
constexpr double T0_D  = ISO_D - FOV_D;
constexpr double DT_D  = 2.0 * FOV_D / NSAMP;

constexpr float DGAMMA  = (float)(DET_D / SDD_D);
constexpr float T0F     = (float)T0_D;
constexpr float DTF     = (float)DT_D;
constexpr float INV_PIX = (float)(1.0 / PIX_D);
constexpr float PI_F    = 3.14159265358979323846f;
}

// 516*516 pixel-groups, 16 bytes each (8 batches x fp16) = 4.26 MB per copy.
__device__ uint4 g_packed[PADN * PADN];   // [y][x]
__device__ uint4 g_packedT[PADN * PADN];  // [x][y]

__global__ void repack_kernel(const float* __restrict__ img) {
    int idx = blockIdx.x * blockDim.x + threadIdx.x;
    if (idx >= PADN * PADN) return;
    int py = idx / PADN;
    int px = idx - py * PADN;
    int y = py - PAD;
    int x = px - PAD;
    uint4 u = make_uint4(0u, 0u, 0u, 0u);
    if ((unsigned)y < (unsigned)IMG && (unsigned)x < (unsigned)IMG) {
        int base = y * IMG + x;
        const int BS = IMG * IMG;
        __half2 h0 = __floats2half2_rn(img[base + 0 * BS], img[base + 1 * BS]);
        __half2 h1 = __floats2half2_rn(img[base + 2 * BS], img[base + 3 * BS]);
        __half2 h2 = __floats2half2_rn(img[base + 4 * BS], img[base + 5 * BS]);
        __half2 h3 = __floats2half2_rn(img[base + 6 * BS], img[base + 7 * BS]);
        u.x = *reinterpret_cast<unsigned*>(&h0);
        u.y = *reinterpret_cast<unsigned*>(&h1);
        u.z = *reinterpret_cast<unsigned*>(&h2);
        u.w = *reinterpret_cast<unsigned*>(&h3);
    }
    g_packed[py * PADN + px] = u;
    g_packedT[px * PADN + py] = u;
}

__device__ __forceinline__ void acc8(uint4 r, float w, float acc[NB]) {
    __half2 h0 = *reinterpret_cast<__half2*>(&r.x);
    __half2 h1 = *reinterpret_cast<__half2*>(&r.y);
    __half2 h2 = *reinterpret_cast<__half2*>(&r.z);
    __half2 h3 = *reinterpret_cast<__half2*>(&r.w);
    float2 f0 = __half22float2(h0);
    float2 f1 = __half22float2(h1);
    float2 f2 = __half22float2(h2);
    float2 f3 = __half22float2(h3);
    acc[0] = fmaf(f0.x, w, acc[0]);
    acc[1] = fmaf(f0.y, w, acc[1]);
    acc[2] = fmaf(f1.x, w, acc[2]);
    acc[3] = fmaf(f1.y, w, acc[3]);
    acc[4] = fmaf(f2.x, w, acc[4]);
    acc[5] = fmaf(f2.y, w, acc[5]);
    acc[6] = fmaf(f3.x, w, acc[6]);
    acc[7] = fmaf(f3.y, w, acc[7]);
}

struct Sample {
    uint4 r00, r01, r10, r11;
    float w00, w01, w10, w11;
};

__device__ __forceinline__ void sample_load(const uint4* __restrict__ pk,
                                            float fu, float fv, Sample& s) {
    // fu = slow axis coordinate, fv = fast (contiguous) axis coordinate
    float u0f = floorf(fu);
    float v0f = floorf(fv);
    float wu = fu - u0f;
    float wv = fv - v0f;
    int u0 = (int)u0f;
    int v0 = (int)v0f;
    u0 = min(max(u0, -PAD), IMG);
    v0 = min(max(v0, -PAD), IMG);
    const uint4* p = pk + (u0 + PAD) * PADN + (v0 + PAD);
    s.r00 = __ldg(p);
    s.r01 = __ldg(p + 1);
    s.r10 = __ldg(p + PADN);
    s.r11 = __ldg(p + PADN + 1);
    float wu1 = 1.0f - wu;
    float wv1 = 1.0f - wv;
    s.w00 = wu1 * wv1;
    s.w01 = wu1 * wv;
    s.w10 = wu * wv1;
    s.w11 = wu * wv;
}

__device__ __forceinline__ void sample_acc(const Sample& s, float acc[NB]) {
    acc8(s.r00, s.w00, acc);
    acc8(s.r01, s.w01, acc);
    acc8(s.r10, s.w10, acc);
    acc8(s.r11, s.w11, acc);
}

// Block = 128 threads = 4 warps. Warp covers 8 detectors x 4 sample phases.
// Block covers 32 detectors of one view.
__global__ __launch_bounds__(128) void proj_kernel(const float* __restrict__ views,
                                                   float* __restrict__ out) {
    const int lane = threadIdx.x & 31;
    const int warp = threadIdx.x >> 5;
    const int dsub = lane & 7;    // detector within warp
    const int soff = lane >> 3;   // sample phase 0..3

    const int d = blockIdx.x * 32 + warp * 8 + dsub;  // detector
    const int v = blockIdx.y;                          // view

    const float beta  = __ldg(&views[v]);
    const float gamma = ((float)d - (float)(NDET - 1) * 0.5f) * DGAMMA;

    float sb, cb;
    sincosf(beta, &sb, &cb);
    const float sx = (float)ISO_D * cb;
    const float sy = (float)ISO_D * sb;

    float diry, dirx;
    sincosf(beta + PI_F + gamma, &diry, &dirx);

    // Pixel-space ray: fx(i) = ax + bx*i (i = sample index)
    const float tstart = T0F + 0.5f * DTF;
    float bx = dirx * DTF * INV_PIX;
    float by = diry * DTF * INV_PIX;
    float ax = (sx + dirx * tstart) * INV_PIX + (float)(IMG - 1) * 0.5f;
    float ay = (sy + diry * tstart) * INV_PIX + (float)(IMG - 1) * 0.5f;

    // Clip sample range to the support box fx,fy in [-1.5, 512.5]
    float flo = 0.0f, fhi = (float)(NSAMP - 1);
    const float LOB = -1.5f, HIB = (float)IMG + 0.5f;
    if (fabsf(bx) > 1e-7f) {
        float r  = 1.0f / bx;
        float t1 = (LOB - ax) * r;
        float t2 = (HIB - ax) * r;
        flo = fmaxf(flo, fminf(t1, t2));
        fhi = fminf(fhi, fmaxf(t1, t2));
    } else if (ax < LOB || ax > HIB) {
        fhi = -1.0f;
    }
    if (fabsf(by) > 1e-7f) {
        float r  = 1.0f / by;
        float t1 = (LOB - ay) * r;
        float t2 = (HIB - ay) * r;
        flo = fmaxf(flo, fminf(t1, t2));
        fhi = fminf(fhi, fmaxf(t1, t2));
    } else if (ay < LOB || ay > HIB) {
        fhi = -1.0f;
    }
    int i0 = max(0, (int)ceilf(flo) - 1);
    int i1 = min(NSAMP, (int)floorf(fhi) + 2);

    // Layout pick: if ray runs mostly along x, perpendicular (dominant) spread
    // is along y -> use transposed layout (fast axis = y). Warp-uniform.
    bool wantT = fabsf(bx) >= fabsf(by);
    wantT = __shfl_sync(0xffffffffu, (int)wantT, 0) != 0;

    const uint4* __restrict__ pk;
    float au, bu, av, bv;  // u = slow axis, v = fast axis of chosen layout
    if (wantT) {
        pk = g_packedT;     // [x][y]
        au = ax; bu = bx;
        av = ay; bv = by;
    } else {
        pk = g_packed;      // [y][x]
        au = ay; bu = by;
        av = ax; bv = bx;
    }

    float acc[NB];
#pragma unroll
    for (int b = 0; b < NB; b++) acc[b] = 0.0f;

    // Lane handles samples i0+soff, i0+soff+4, ... Unroll x2 (stride 8).
    int i = i0 + soff;
    for (; i + 4 < i1; i += 8) {
        float f0 = (float)i;
        float f1 = (float)(i + 4);
        Sample s0, s1;
        sample_load(pk, fmaf(f0, bu, au), fmaf(f0, bv, av), s0);
        sample_load(pk, fmaf(f1, bu, au), fmaf(f1, bv, av), s1);
        sample_acc(s0, acc);
        sample_acc(s1, acc);
    }
    if (i < i1) {
        float f0 = (float)i;
        Sample s0;
        sample_load(pk, fmaf(f0, bu, au), fmaf(f0, bv, av), s0);
        sample_acc(s0, acc);
    }

    // Merge the 4 sample-phase partials (lanes dsub, dsub+8, dsub+16, dsub+24).
#pragma unroll
    for (int b = 0; b < NB; b++) {
        acc[b] += __shfl_xor_sync(0xffffffffu, acc[b], 8);
        acc[b] += __shfl_xor_sync(0xffffffffu, acc[b], 16);
    }

    if (soff == 0) {
#pragma unroll
        for (int b = 0; b < NB; b++) {
            out[(b * NVIEWS + v) * NDET + d] = acc[b] * DTF;
        }
    }
}

extern "C" void kernel_launch(void* const* d_in, const int* in_sizes, int n_in,
                              void* d_out, int out_size) {
    const float* image = (const float*)d_in[0];
    const float* views = (const float*)d_in[1];
    float* out = (float*)d_out;

    repack_kernel<<<(PADN * PADN + 255) / 256, 256>>>(image);
    proj_kernel<<<dim3(NDET / 32, NVIEWS), 128>>>(views, out);
}

// round 5
// speedup vs baseline: 2.1894x; 1.6949x over previous
#include <cuda_runtime.h>
#include <cuda_fp16.h>

// Fan-beam CT forward projector.
// image [8,512,512] f32, views [360] f32 -> out [8,360,768] f32.
//
// R4: u8-quantized image, fast-axis PAIR packing (entry = 8 batches x {v,v+1}
// u8 = 16B), dual layouts. One bilinear sample = 2x LDG.128 + 16x dp4a with
// u8 weights, integer accumulation. Warp = 8 det x 4 sample phases.

namespace {
constexpr int IMG    = 512;
constexpr int PAD    = 2;
constexpr int PADN   = IMG + 2 * PAD;   // 516
constexpr int NB     = 8;
constexpr int NDET   = 768;
constexpr int NVIEWS = 360;
constexpr int NSAMP  = 768;

constexpr double PIX_D = 0.7433;
constexpr double DET_D = 1.2858;
constexpr double ISO_D = 595.0;
constexpr double SDD_D = 595.0 + 490.6;
constexpr double FOV_D = IMG * PIX_D * 0.70710678;
constexpr double T0_D  = ISO_D - FOV_D;
constexpr double DT_D  = 2.0 * FOV_D / NSAMP;

constexpr float DGAMMA  = (float)(DET_D / SDD_D);
constexpr float T0F     = (float)T0_D;
constexpr float DTF     = (float)DT_D;
constexpr float INV_PIX = (float)(1.0 / PIX_D);
constexpr float PI_F    = 3.14159265358979323846f;
}

// entry[u][v]: word k = b(2k)@v | b(2k)@(v+1)<<8 | b(2k+1)@v<<16 | b(2k+1)@(v+1)<<24
// 516*516 entries x 16B = 4.26 MB per layout.
__device__ uint4 g_packA[PADN * PADN];   // slow=y, fast=x
__device__ uint4 g_packB[PADN * PADN];   // slow=x, fast=y

__device__ __forceinline__ void pix_u8(const float* __restrict__ img,
                                       int y, int x, unsigned v8[NB]) {
    const int BS = IMG * IMG;
    bool ok = (unsigned)y < (unsigned)IMG && (unsigned)x < (unsigned)IMG;
    int base = ok ? (y * IMG + x) : 0;
#pragma unroll
    for (int b = 0; b < NB; b++) {
        v8[b] = ok ? __float2uint_rn(img[b * BS + base] * 255.0f) : 0u;
    }
}

__device__ __forceinline__ uint4 pack_pair(const unsigned a[NB], const unsigned b[NB]) {
    uint4 u;
    u.x = a[0] | (b[0] << 8) | (a[1] << 16) | (b[1] << 24);
    u.y = a[2] | (b[2] << 8) | (a[3] << 16) | (b[3] << 24);
    u.z = a[4] | (b[4] << 8) | (a[5] << 16) | (b[5] << 24);
    u.w = a[6] | (b[6] << 8) | (a[7] << 16) | (b[7] << 24);
    return u;
}

__global__ void repack_kernel(const float* __restrict__ img) {
    int idx = blockIdx.x * blockDim.x + threadIdx.x;
    if (idx >= PADN * PADN) return;
    int pu = idx / PADN;
    int pv = idx - pu * PADN;
    int u = pu - PAD;
    int v = pv - PAD;

    unsigned p00[NB], pA1[NB], pB1[NB];
    pix_u8(img, u, v, p00);       // (y=u, x=v)
    pix_u8(img, u, v + 1, pA1);   // fast=x neighbor
    pix_u8(img, v + 1, u, pB1);   // for layout B: pixel(y=v+1, x=u)

    // Layout A: entryA[y=u][x=v] = pair along x: (y,x),(y,x+1)
    g_packA[pu * PADN + pv] = pack_pair(p00, pA1);

    // Layout B: entryB[x][y] = pair along y: (y,x),(y+1,x).
    // At B-index [pu][pv]: slow u = x, fast v = y -> pixels (y=v,x=u),(y=v+1,x=u).
    unsigned q0[NB];
    pix_u8(img, v, u, q0);
    g_packB[pu * PADN + pv] = pack_pair(q0, pB1);
}

struct Sample {
    uint4 r0, r1;                 // row u0, row u0+1 pair-entries
    unsigned m0, m1, m2, m3;      // dp4a weight masks
};

__device__ __forceinline__ void sample_load(const uint4* __restrict__ pk,
                                            float fu, float fv, Sample& s) {
    float u0f = floorf(fu);
    float v0f = floorf(fv);
    float wu = fu - u0f;
    float wv = fv - v0f;
    int u0 = (int)u0f;
    int v0 = (int)v0f;
    u0 = min(max(u0, -PAD), IMG);
    v0 = min(max(v0, -PAD), IMG);
    const uint4* p = pk + (u0 + PAD) * PADN + (v0 + PAD);
    s.r0 = __ldg(p);
    s.r1 = __ldg(p + PADN);
    float wu1 = 1.0f - wu;
    float wv1 = 1.0f - wv;
    unsigned w00 = (unsigned)__float2int_rn(wu1 * wv1 * 255.0f);
    unsigned w01 = (unsigned)__float2int_rn(wu1 * wv * 255.0f);
    unsigned w10 = (unsigned)__float2int_rn(wu * wv1 * 255.0f);
    unsigned w11 = (unsigned)__float2int_rn(wu * wv * 255.0f);
    s.m0 = w00 | (w01 << 8);
    s.m1 = s.m0 << 16;
    s.m2 = w10 | (w11 << 8);
    s.m3 = s.m2 << 16;
}

__device__ __forceinline__ void sample_acc(const Sample& s, unsigned acc[NB]) {
    acc[0] = __dp4a(s.r0.x, s.m0, acc[0]);
    acc[1] = __dp4a(s.r0.x, s.m1, acc[1]);
    acc[2] = __dp4a(s.r0.y, s.m0, acc[2]);
    acc[3] = __dp4a(s.r0.y, s.m1, acc[3]);
    acc[4] = __dp4a(s.r0.z, s.m0, acc[4]);
    acc[5] = __dp4a(s.r0.z, s.m1, acc[5]);
    acc[6] = __dp4a(s.r0.w, s.m0, acc[6]);
    acc[7] = __dp4a(s.r0.w, s.m1, acc[7]);
    acc[0] = __dp4a(s.r1.x, s.m2, acc[0]);
    acc[1] = __dp4a(s.r1.x, s.m3, acc[1]);
    acc[2] = __dp4a(s.r1.y, s.m2, acc[2]);
    acc[3] = __dp4a(s.r1.y, s.m3, acc[3]);
    acc[4] = __dp4a(s.r1.z, s.m2, acc[4]);
    acc[5] = __dp4a(s.r1.z, s.m3, acc[5]);
    acc[6] = __dp4a(s.r1.w, s.m2, acc[6]);
    acc[7] = __dp4a(s.r1.w, s.m3, acc[7]);
}

// Block = 128 threads = 4 warps. Warp covers 8 detectors x 4 sample phases.
__global__ __launch_bounds__(128) void proj_kernel(const float* __restrict__ views,
                                                   float* __restrict__ out) {
    const int lane = threadIdx.x & 31;
    const int warp = threadIdx.x >> 5;
    const int dsub = lane & 7;    // detector within warp
    const int soff = lane >> 3;   // sample phase 0..3

    const int d = blockIdx.x * 32 + warp * 8 + dsub;  // detector
    const int v = blockIdx.y;                          // view

    const float beta  = __ldg(&views[v]);
    const float gamma = ((float)d - (float)(NDET - 1) * 0.5f) * DGAMMA;

    float sb, cb;
    sincosf(beta, &sb, &cb);
    const float sx = (float)ISO_D * cb;
    const float sy = (float)ISO_D * sb;

    float diry, dirx;
    sincosf(beta + PI_F + gamma, &diry, &dirx);

    const float tstart = T0F + 0.5f * DTF;
    float bx = dirx * DTF * INV_PIX;
    float by = diry * DTF * INV_PIX;
    float ax = (sx + dirx * tstart) * INV_PIX + (float)(IMG - 1) * 0.5f;
    float ay = (sy + diry * tstart) * INV_PIX + (float)(IMG - 1) * 0.5f;

    // Clip sample range to the support box fx,fy in [-1.5, 512.5]
    float flo = 0.0f, fhi = (float)(NSAMP - 1);
    const float LOB = -1.5f, HIB = (float)IMG + 0.5f;
    if (fabsf(bx) > 1e-7f) {
        float r  = 1.0f / bx;
        float t1 = (LOB - ax) * r;
        float t2 = (HIB - ax) * r;
        flo = fmaxf(flo, fminf(t1, t2));
        fhi = fminf(fhi, fmaxf(t1, t2));
    } else if (ax < LOB || ax > HIB) {
        fhi = -1.0f;
    }
    if (fabsf(by) > 1e-7f) {
        float r  = 1.0f / by;
        float t1 = (LOB - ay) * r;
        float t2 = (HIB - ay) * r;
        flo = fmaxf(flo, fminf(t1, t2));
        fhi = fminf(fhi, fmaxf(t1, t2));
    } else if (ay < LOB || ay > HIB) {
        fhi = -1.0f;
    }
    int i0 = max(0, (int)ceilf(flo) - 1);
    int i1 = min(NSAMP, (int)floorf(fhi) + 2);

    // Layout pick (warp-uniform): ray along x -> lanes spread along y -> layout B.
    bool wantB = fabsf(bx) >= fabsf(by);
    wantB = __shfl_sync(0xffffffffu, (int)wantB, 0) != 0;

    const uint4* __restrict__ pk;
    float au, bu, av, bv;  // u = slow axis, v = fast axis of chosen layout
    if (wantB) {
        pk = g_packB;       // slow=x, fast=y
        au = ax; bu = bx;
        av = ay; bv = by;
    } else {
        pk = g_packA;       // slow=y, fast=x
        au = ay; bu = by;
        av = ax; bv = bx;
    }

    unsigned acc[NB];
#pragma unroll
    for (int b = 0; b < NB; b++) acc[b] = 0u;

    int i = i0 + soff;
    for (; i + 4 < i1; i += 8) {
        float f0 = (float)i;
        float f1 = (float)(i + 4);
        Sample s0, s1;
        sample_load(pk, fmaf(f0, bu, au), fmaf(f0, bv, av), s0);
        sample_load(pk, fmaf(f1, bu, au), fmaf(f1, bv, av), s1);
        sample_acc(s0, acc);
        sample_acc(s1, acc);
    }
    if (i < i1) {
        float f0 = (float)i;
        Sample s0;
        sample_load(pk, fmaf(f0, bu, au), fmaf(f0, bv, av), s0);
        sample_acc(s0, acc);
    }

    // Merge the 4 sample-phase partials (exact integer adds).
#pragma unroll
    for (int b = 0; b < NB; b++) {
        acc[b] += __shfl_xor_sync(0xffffffffu, acc[b], 8);
        acc[b] += __shfl_xor_sync(0xffffffffu, acc[b], 16);
    }

    if (soff == 0) {
        const float scale = DTF / (255.0f * 255.0f);
#pragma unroll
        for (int b = 0; b < NB; b++) {
            out[(b * NVIEWS + v) * NDET + d] = (float)acc[b] * scale;
        }
    }
}

extern "C" void kernel_launch(void* const* d_in, const int* in_sizes, int n_in,
                              void* d_out, int out_size) {
    const float* image = (const float*)d_in[0];
    const float* views = (const float*)d_in[1];
    float* out = (float*)d_out;

    repack_kernel<<<(PADN * PADN + 255) / 256, 256>>>(image);
    proj_kernel<<<dim3(NDET / 32, NVIEWS), 128>>>(views, out);
}